// round 10
// baseline (speedup 1.0000x reference)
#include <cuda_runtime.h>
#include <cuda_fp16.h>
#include <cstdint>

#define Nn    512
#define NN    (Nn * Nn)
#define BATCH 64
#define BM 64
#define BN 64
#define MAT_A 8192               // 64 rows x 128B [ArH k32 | AiH k32]
#define STG16 16384              // stage: A (8KB) + X (8KB)
#define NSTG 4                   // 2 per group
#define SMEM_BYTES (NSTG * STG16 + 1024)
#define NMYC 8                   // k32 chunks per group (16 total, split by parity)

// ---------------- global scratch ----------------
__device__ __half g_xt_h[(size_t)BATCH * 2 * NN];   // X^T single fp16
__device__ __half g_s0_h[(size_t)BATCH * 2 * NN];   // S ping-pong, single fp16
__device__ __half g_s1_h[(size_t)BATCH * 2 * NN];
__device__ __half g_c7_h[(size_t)2 * NN];

// ---------------- helpers ----------------
__device__ __forceinline__ uint32_t smem_u32(const void* p) {
    uint32_t a;
    asm("{ .reg .u64 t; cvta.to.shared.u64 t, %1; cvt.u32.u64 %0, t; }" : "=r"(a) : "l"(p));
    return a;
}
#define CP_ASYNC16(dst, src) \
    asm volatile("cp.async.cg.shared.global [%0], [%1], 16;" :: "r"(dst), "l"(src))
#define CP_COMMIT()  asm volatile("cp.async.commit_group;" ::: "memory")
#define CP_WAIT0()   asm volatile("cp.async.wait_group 0;" ::: "memory")
#define GBAR(id)     asm volatile("bar.sync %0, 128;" :: "r"(id) : "memory")

__device__ __forceinline__ void ldsm4(uint32_t* r, uint32_t addr) {
    asm volatile("ldmatrix.sync.aligned.m8n8.x4.shared.b16 {%0,%1,%2,%3}, [%4];"
                 : "=r"(r[0]), "=r"(r[1]), "=r"(r[2]), "=r"(r[3]) : "r"(addr));
}
__device__ __forceinline__ void mma16816(float* d, const uint32_t* a, const uint32_t* b) {
    asm volatile(
        "mma.sync.aligned.m16n8k16.row.col.f32.f16.f16.f32 "
        "{%0,%1,%2,%3}, {%4,%5,%6,%7}, {%8,%9}, {%0,%1,%2,%3};"
        : "+f"(d[0]), "+f"(d[1]), "+f"(d[2]), "+f"(d[3])
        : "r"(a[0]), "r"(a[1]), "r"(a[2]), "r"(a[3]), "r"(b[0]), "r"(b[1]));
}

// ---------------------------------------------------------------------------
__global__ void x_transpose_h(const float* __restrict__ x,
                              __half* __restrict__ xh)
{
    __shared__ float t[32][33];
    const int z  = blockIdx.z;
    const int k0 = blockIdx.y * 32;
    const int n0 = blockIdx.x * 32;
    const int tx = threadIdx.x & 31, ty = threadIdx.x >> 5;
    const long zb = (long)z * NN;
    #pragma unroll
    for (int i = 0; i < 4; ++i)
        t[ty + 8 * i][tx] = x[zb + (long)(k0 + ty + 8 * i) * Nn + n0 + tx];
    __syncthreads();
    #pragma unroll
    for (int i = 0; i < 4; ++i) {
        const int n = n0 + ty + 8 * i, k = k0 + tx;
        xh[zb + (long)n * Nn + k] = __float2half_rn(t[tx][ty + 8 * i]);
    }
}

__global__ void conv_c7(const float* __restrict__ c7, __half* __restrict__ h)
{
    const int i = blockIdx.x * 256 + threadIdx.x;
    if (i < 2 * NN) h[i] = __float2half_rn(c7[i]);
}

// ---------------------------------------------------------------------------
// Fused complex GEMM, single-fp16, 4 passes, ANTI-PHASE WARP GROUPS:
// 8 warps = 2 groups of 4; group g handles k32 chunks with parity g.
// Each group: own 2 smem stages, own named barrier, own cp.async stream.
// While one group drains/ramps at its barrier, the other's mma fills the
// tensor pipe (each SMSP hosts one warp of each group per CTA).
// Group partial sums merged through smem at the end; group 0 does epilogue.
// ---------------------------------------------------------------------------
__global__ void __launch_bounds__(256, 2) cgemm_mma(
    const __half* __restrict__ aH, long aStride,
    const __half* __restrict__ xH,
    const float* __restrict__ C,
    float* __restrict__ outF,
    __half* __restrict__ outH,
    int isFinal)
{
    extern __shared__ char smraw[];
    const uint32_t sbase = (smem_u32(smraw) + 1023) & ~1023u;

    const int tid  = threadIdx.x;
    const int lane = tid & 31, wid = tid >> 5;
    const int g    = wid >> 2;           // group 0/1
    const int gw   = wid & 3;            // warp in group
    const int warp_m = gw & 1;           // 2 m-tiles of 32
    const int warp_n = gw >> 1;          // 2 n-tiles of 32
    const int b  = blockIdx.z;
    const int bn = blockIdx.x * BN;
    const int bm = blockIdx.y * BM;

    // Per-CTA k-phase within each parity class.
    const int phase =
        (int)(((blockIdx.x + blockIdx.y * 8u + blockIdx.z * 64u) * 5u) & 7u);

    // ---- cp.async constants (per group: 128 threads, 16KB/chunk) ----
    const int gtid = tid & 127;
    const int q = gtid & 7, rowt = gtid >> 3;   // rowt 0..15
    const int comp = q >> 2;
    const __half* srcA = aH + (long)b * aStride + (long)comp * NN
                       + (long)(bm + rowt) * Nn + (q & 3) * 8;
    const __half* srcX = xH + ((long)(2 * b) + comp) * NN
                       + (long)(bn + rowt) * Nn + (q & 3) * 8;
    const uint32_t dA0 = ((uint32_t)(rowt * 128 + q * 16)) ^ (uint32_t)((rowt & 7) << 4);
    const uint32_t dX0 = (uint32_t)MAT_A + dA0;
    const uint32_t gsb = sbase + (uint32_t)(g * 2) * STG16;

    auto issue = [&](int myc) {
        const uint32_t sd = gsb + (uint32_t)(myc & 1) * STG16;
        const int kidx = (2 * ((myc + phase) & 7) + g) & 15;
        const long kadd = (long)kidx * 32;
        #pragma unroll
        for (int it = 0; it < 4; ++it)
            CP_ASYNC16(sd + dA0 + (uint32_t)it * 2048u, srcA + kadd + (long)it * 16 * Nn);
        #pragma unroll
        for (int it = 0; it < 4; ++it)
            CP_ASYNC16(sd + dX0 + (uint32_t)it * 2048u, srcX + kadd + (long)it * 16 * Nn);
        CP_COMMIT();
    };

    // ---- ldmatrix per-lane constants ----
    const uint32_t amask = (uint32_t)((lane & 7) << 4);
    const uint32_t abase = (uint32_t)((warp_m * 32 + (lane & 15)) * 128 + (lane >> 4) * 16);
    const uint32_t brow  = (uint32_t)((lane & 7) | ((lane >> 1) & 8));
    const uint32_t bcol  = (uint32_t)(((lane >> 3) & 1) * 16);

    float accD[2][4][4], accM[2][4][4];
    #pragma unroll
    for (int i = 0; i < 2; ++i)
        #pragma unroll
        for (int j = 0; j < 4; ++j)
            #pragma unroll
            for (int k = 0; k < 4; ++k) { accD[i][j][k] = 0.f; accM[i][j][k] = 0.f; }

    issue(0);

    for (int myc = 0; myc < NMYC; ++myc) {
        CP_WAIT0();                 // this thread's chunk myc copies done
        GBAR(g + 1);                // whole group's copies done + prev readers retired
        if (myc + 1 < NMYC) issue(myc + 1);   // stage freed by the barrier

        const uint32_t st = gsb + (uint32_t)(myc & 1) * STG16;
        #pragma unroll
        for (int sl = 0; sl < 2; ++sl) {
            uint32_t ar[2][4], ai[2][4], an[2][4];
            #pragma unroll
            for (int mt = 0; mt < 2; ++mt) {
                const uint32_t rh =
                    (abase + (uint32_t)mt * 2048u + (uint32_t)sl * 32u) ^ amask;
                ldsm4(ar[mt], st + rh);             // Ar half
                ldsm4(ai[mt], st + (rh ^ 64u));     // Ai half
                #pragma unroll
                for (int j = 0; j < 4; ++j) an[mt][j] = ai[mt][j] ^ 0x80008000u;
            }
            #pragma unroll
            for (int ng = 0; ng < 2; ++ng) {
                const uint32_t bb =
                    ((uint32_t)((warp_n * 32 + ng * 16 + brow) * 128) + bcol
                     + (uint32_t)sl * 32u) ^ amask;
                uint32_t br[4], bi[4];
                ldsm4(br, st + (uint32_t)MAT_A + bb);            // Xr half
                ldsm4(bi, st + (uint32_t)MAT_A + (bb ^ 64u));    // Xi half
                #pragma unroll
                for (int mt = 0; mt < 2; ++mt)
                    #pragma unroll
                    for (int nt = 0; nt < 2; ++nt) {
                        float* dd = accD[mt][ng * 2 + nt];
                        float* mm = accM[mt][ng * 2 + nt];
                        mma16816(dd, ar[mt], br + nt * 2);
                        mma16816(dd, an[mt], bi + nt * 2);
                        mma16816(mm, ai[mt], br + nt * 2);
                        mma16816(mm, ar[mt], bi + nt * 2);
                    }
            }
        }
    }

    // ---- merge group partial sums through smem (reuse stages 0-1: 32KB) ----
    __syncthreads();                        // all mainloop reads done
    if (g == 1) {
        const uint32_t wb = sbase + (uint32_t)gw * 8192u + (uint32_t)lane * 16u;
        int idx = 0;
        #pragma unroll
        for (int mt = 0; mt < 2; ++mt)
            #pragma unroll
            for (int j = 0; j < 4; ++j) {
                asm volatile("st.shared.v4.f32 [%0], {%1,%2,%3,%4};"
                    :: "r"(wb + idx * 512u), "f"(accD[mt][j][0]), "f"(accD[mt][j][1]),
                       "f"(accD[mt][j][2]), "f"(accD[mt][j][3]) : "memory");
                ++idx;
            }
        #pragma unroll
        for (int mt = 0; mt < 2; ++mt)
            #pragma unroll
            for (int j = 0; j < 4; ++j) {
                asm volatile("st.shared.v4.f32 [%0], {%1,%2,%3,%4};"
                    :: "r"(wb + idx * 512u), "f"(accM[mt][j][0]), "f"(accM[mt][j][1]),
                       "f"(accM[mt][j][2]), "f"(accM[mt][j][3]) : "memory");
                ++idx;
            }
    }
    __syncthreads();

    if (g == 0) {
        const uint32_t wb = sbase + (uint32_t)gw * 8192u + (uint32_t)lane * 16u;
        int idx = 0;
        #pragma unroll
        for (int mt = 0; mt < 2; ++mt)
            #pragma unroll
            for (int j = 0; j < 4; ++j) {
                float4 v;
                asm volatile("ld.shared.v4.f32 {%0,%1,%2,%3}, [%4];"
                    : "=f"(v.x), "=f"(v.y), "=f"(v.z), "=f"(v.w)
                    : "r"(wb + idx * 512u));
                accD[mt][j][0] += v.x; accD[mt][j][1] += v.y;
                accD[mt][j][2] += v.z; accD[mt][j][3] += v.w;
                ++idx;
            }
        #pragma unroll
        for (int mt = 0; mt < 2; ++mt)
            #pragma unroll
            for (int j = 0; j < 4; ++j) {
                float4 v;
                asm volatile("ld.shared.v4.f32 {%0,%1,%2,%3}, [%4];"
                    : "=f"(v.x), "=f"(v.y), "=f"(v.z), "=f"(v.w)
                    : "r"(wb + idx * 512u));
                accM[mt][j][0] += v.x; accM[mt][j][1] += v.y;
                accM[mt][j][2] += v.z; accM[mt][j][3] += v.w;
                ++idx;
            }

        // ---- epilogue: Dr = accD + Cr ; Di = accM + Ci ----
        const int tq = lane >> 2, tr = (lane & 3) * 2;
        #pragma unroll
        for (int mt = 0; mt < 2; ++mt)
            #pragma unroll
            for (int j = 0; j < 4; ++j)
                #pragma unroll
                for (int h = 0; h < 2; ++h) {
                    const int r  = bm + warp_m * 32 + mt * 16 + h * 8 + tq;
                    const int c0 = bn + warp_n * 32 + j * 8 + tr;
                    const long co = (long)r * Nn + c0;
                    const float2 cr = *(const float2*)(C + co);
                    const float2 ci = *(const float2*)(C + NN + co);
                    const float vr0 = accD[mt][j][2*h]   + cr.x;
                    const float vr1 = accD[mt][j][2*h+1] + cr.y;
                    const float vi0 = accM[mt][j][2*h]   + ci.x;
                    const float vi1 = accM[mt][j][2*h+1] + ci.y;
                    const long or_ = ((long)b * 2 + 0) * NN + co;
                    const long oi_ = ((long)b * 2 + 1) * NN + co;
                    if (isFinal) {
                        *(float2*)(outF + or_) = make_float2(vr0, vr1);
                        *(float2*)(outF + oi_) = make_float2(vi0, vi1);
                    } else {
                        __half2 hv;
                        hv.x = __float2half_rn(vr0); hv.y = __float2half_rn(vr1);
                        *(__half2*)(outH + or_) = hv;
                        hv.x = __float2half_rn(vi0); hv.y = __float2half_rn(vi1);
                        *(__half2*)(outH + oi_) = hv;
                    }
                }
    }
}

// ---------------------------------------------------------------------------
extern "C" void kernel_launch(void* const* d_in, const int* in_sizes, int n_in,
                              void* d_out, int out_size)
{
    const float* x      = (const float*)d_in[0];
    const float* coeffs = (const float*)d_in[1];
    if (n_in >= 2 && in_sizes[0] == 8 * 2 * NN) {
        const float* t = x; x = coeffs; coeffs = t;
    }

    __half *xtH, *s0H, *s1H, *c7H;
    cudaGetSymbolAddress((void**)&xtH, g_xt_h);
    cudaGetSymbolAddress((void**)&s0H, g_s0_h);
    cudaGetSymbolAddress((void**)&s1H, g_s1_h);
    cudaGetSymbolAddress((void**)&c7H, g_c7_h);

    cudaFuncSetAttribute(cgemm_mma, cudaFuncAttributeMaxDynamicSharedMemorySize, SMEM_BYTES);

    x_transpose_h<<<dim3(16, 16, 128), 256>>>(x, xtH);
    conv_c7<<<(2 * NN + 255) / 256, 256>>>(coeffs + (long)7 * 2 * NN, c7H);

    dim3 grid(Nn / BN, Nn / BM, BATCH);   // (8, 8, 64)
    dim3 block(256);

    const __half* aP = c7H;
    long aStride = 0;
    __half* dstH[7] = {s0H, s1H, s0H, s1H, s0H, s1H, nullptr};

    for (int t = 0; t < 7; ++t) {
        const float* Ct = coeffs + (long)(6 - t) * 2 * NN;
        const int fin = (t == 6);
        cgemm_mma<<<grid, block, SMEM_BYTES>>>(
            aP, aStride, xtH, Ct,
            fin ? (float*)d_out : nullptr, dstH[t], fin);
        aP = dstH[t];
        aStride = 2L * NN;
    }
}

// round 11
// speedup vs baseline: 1.0185x; 1.0185x over previous
#include <cuda_runtime.h>
#include <cuda_fp16.h>
#include <cstdint>

#define Nn    512
#define NN    (Nn * Nn)
#define BATCH 64
#define KCH   32
#define NCHUNK (Nn / KCH)        // 16
#define BM 64
#define BN 64
#define MAT_A 8192               // 64 rows x 128B [ArH k32 | AiH k32]
#define STG_B 16384              // A (8KB) + X (8KB)
#define NSTG 3
#define SMEM_BYTES (NSTG * STG_B + 1024)

// ---------------- global scratch ----------------
__device__ __half g_xt_h[(size_t)BATCH * 2 * NN];   // X^T single fp16
__device__ __half g_s0_h[(size_t)BATCH * 2 * NN];   // S ping-pong, single fp16
__device__ __half g_s1_h[(size_t)BATCH * 2 * NN];
__device__ __half g_c7_h[(size_t)2 * NN];

// ---------------- helpers ----------------
__device__ __forceinline__ uint32_t smem_u32(const void* p) {
    uint32_t a;
    asm("{ .reg .u64 t; cvta.to.shared.u64 t, %1; cvt.u32.u64 %0, t; }" : "=r"(a) : "l"(p));
    return a;
}
#define CP_ASYNC16(dst, src) \
    asm volatile("cp.async.cg.shared.global [%0], [%1], 16;" :: "r"(dst), "l"(src))
#define CP_COMMIT()  asm volatile("cp.async.commit_group;" ::: "memory")
#define CP_WAIT1()   asm volatile("cp.async.wait_group 1;" ::: "memory")
#define CP_WAIT0()   asm volatile("cp.async.wait_group 0;" ::: "memory")

__device__ __forceinline__ void ldsm4(uint32_t* r, uint32_t addr) {
    asm volatile("ldmatrix.sync.aligned.m8n8.x4.shared.b16 {%0,%1,%2,%3}, [%4];"
                 : "=r"(r[0]), "=r"(r[1]), "=r"(r[2]), "=r"(r[3]) : "r"(addr));
}
__device__ __forceinline__ void mma16816(float* d, const uint32_t* a, const uint32_t* b) {
    asm volatile(
        "mma.sync.aligned.m16n8k16.row.col.f32.f16.f16.f32 "
        "{%0,%1,%2,%3}, {%4,%5,%6,%7}, {%8,%9}, {%0,%1,%2,%3};"
        : "+f"(d[0]), "+f"(d[1]), "+f"(d[2]), "+f"(d[3])
        : "r"(a[0]), "r"(a[1]), "r"(a[2]), "r"(a[3]), "r"(b[0]), "r"(b[1]));
}

// ---------------------------------------------------------------------------
__global__ void x_transpose_h(const float* __restrict__ x,
                              __half* __restrict__ xh)
{
    __shared__ float t[32][33];
    const int z  = blockIdx.z;
    const int k0 = blockIdx.y * 32;
    const int n0 = blockIdx.x * 32;
    const int tx = threadIdx.x & 31, ty = threadIdx.x >> 5;
    const long zb = (long)z * NN;
    #pragma unroll
    for (int i = 0; i < 4; ++i)
        t[ty + 8 * i][tx] = x[zb + (long)(k0 + ty + 8 * i) * Nn + n0 + tx];
    __syncthreads();
    #pragma unroll
    for (int i = 0; i < 4; ++i) {
        const int n = n0 + ty + 8 * i, k = k0 + tx;
        xh[zb + (long)n * Nn + k] = __float2half_rn(t[tx][ty + 8 * i]);
    }
}

__global__ void conv_c7(const float* __restrict__ c7, __half* __restrict__ h)
{
    const int i = blockIdx.x * 256 + threadIdx.x;
    if (i < 2 * NN) h[i] = __float2half_rn(c7[i]);
}

// ---------------------------------------------------------------------------
// Fused complex GEMM, single-fp16, 4 passes, in the R6 skeleton:
//   accD = Ar.Xr + (-Ai).Xi ; accM = Ai.Xr + Ar.Xi
// CTA 64x64, 8 warps (4m x 2n), warp tile 16x32, 2 CTAs/SM,
// 3-stage cp.async pipeline: WAIT1 -> sync -> compute(sl0) -> issue(c+2)
// -> compute(sl1). Phase-staggered k order per CTA.
// smem rows pack components: A row = [ArH | AiH], X row = [XrH | XiH].
// ---------------------------------------------------------------------------
__global__ void __launch_bounds__(256, 2) cgemm_mma(
    const __half* __restrict__ aH, long aStride,
    const __half* __restrict__ xH,
    const float* __restrict__ C,
    float* __restrict__ outF,
    __half* __restrict__ outH,
    int isFinal)
{
    extern __shared__ char smraw[];
    const uint32_t sbase = (smem_u32(smraw) + 1023) & ~1023u;

    const int tid  = threadIdx.x;
    const int lane = tid & 31, wid = tid >> 5;
    const int warp_m = wid & 3;          // 4 m-tiles of 16 rows
    const int warp_n = wid >> 2;         // 2 n-tiles of 32 cols
    const int b  = blockIdx.z;
    const int bn = blockIdx.x * BN;
    const int bm = blockIdx.y * BM;

    // Per-CTA k-phase: decorrelate barrier timing of co-resident CTAs.
    const int phase =
        (int)(((blockIdx.x + blockIdx.y * 8u + blockIdx.z * 64u) * 11u) & 15u);

    // ---- cp.async per-thread constants: 4 x 16B per thread per chunk ----
    const int q = tid & 7, rowt = tid >> 3;   // q: 16B chunk in 128B row, rowt 0..31
    const int comp = q >> 2;
    const __half* srcs[4];
    uint32_t dsts[4];
    #pragma unroll
    for (int it = 0; it < 4; ++it) {
        const int row = rowt + (it & 1) * 32;
        const uint32_t sw =
            ((uint32_t)(row * 128 + q * 16)) ^ (uint32_t)((row & 7) << 4);
        if (it < 2) {        // A rows 0..63
            srcs[it] = aH + (long)b * aStride + (long)comp * NN
                     + (long)(bm + row) * Nn + (q & 3) * 8;
            dsts[it] = sw;
        } else {             // X rows 0..63
            srcs[it] = xH + ((long)(2 * b) + comp) * NN
                     + (long)(bn + row) * Nn + (q & 3) * 8;
            dsts[it] = (uint32_t)MAT_A + sw;
        }
    }

    auto issue = [&](int c) {
        const uint32_t sd = sbase + (uint32_t)(c % NSTG) * STG_B;
        const long kadd = (long)(((c + phase) & (NCHUNK - 1)) * KCH);
        #pragma unroll
        for (int it = 0; it < 4; ++it)
            CP_ASYNC16(sd + dsts[it], srcs[it] + kadd);
        CP_COMMIT();
    };

    // ---- ldmatrix per-lane constants ----
    const uint32_t amask = (uint32_t)((lane & 7) << 4);
    const uint32_t abase = (uint32_t)((warp_m * 16 + (lane & 15)) * 128 + (lane >> 4) * 16);
    const uint32_t brow  = (uint32_t)((lane & 7) | ((lane >> 1) & 8));
    const uint32_t bcol  = (uint32_t)(((lane >> 3) & 1) * 16);

    float accD[4][4], accM[4][4];
    #pragma unroll
    for (int j = 0; j < 4; ++j)
        #pragma unroll
        for (int k = 0; k < 4; ++k) { accD[j][k] = 0.f; accM[j][k] = 0.f; }

    issue(0); issue(1);

    for (int c = 0; c < NCHUNK; ++c) {
        if (c < NCHUNK - 1) CP_WAIT1(); else CP_WAIT0();
        __syncthreads();

        const uint32_t st = sbase + (uint32_t)(c % NSTG) * STG_B;
        #pragma unroll
        for (int sl = 0; sl < 2; ++sl) {
            uint32_t ar[4], ai[4], an[4];
            const uint32_t rh = (abase + (uint32_t)sl * 32u) ^ amask;
            ldsm4(ar, st + rh);             // Ar half
            ldsm4(ai, st + (rh ^ 64u));     // Ai half
            #pragma unroll
            for (int j = 0; j < 4; ++j) an[j] = ai[j] ^ 0x80008000u;

            #pragma unroll
            for (int ng = 0; ng < 2; ++ng) {
                const uint32_t bb =
                    ((uint32_t)((warp_n * 32 + ng * 16 + brow) * 128) + bcol
                     + (uint32_t)sl * 32u) ^ amask;
                uint32_t br[4], bi[4];
                ldsm4(br, st + (uint32_t)MAT_A + bb);            // Xr half
                ldsm4(bi, st + (uint32_t)MAT_A + (bb ^ 64u));    // Xi half
                #pragma unroll
                for (int nt = 0; nt < 2; ++nt) {
                    float* dd = accD[ng * 2 + nt];
                    float* mm = accM[ng * 2 + nt];
                    mma16816(dd, ar, br + nt * 2);
                    mma16816(dd, an, bi + nt * 2);
                    mma16816(mm, ai, br + nt * 2);
                    mma16816(mm, ar, bi + nt * 2);
                }
            }
            // Launch next chunk's loads after the first slice's ldsm burst.
            if (sl == 0 && c + 2 < NCHUNK) issue(c + 2);
        }
    }

    // ---- epilogue: Dr = accD + Cr ; Di = accM + Ci ----
    const int tq = lane >> 2, tr = (lane & 3) * 2;
    #pragma unroll
    for (int nt8 = 0; nt8 < 4; ++nt8)
        #pragma unroll
        for (int h = 0; h < 2; ++h) {
            const int r  = bm + warp_m * 16 + h * 8 + tq;
            const int c0 = bn + warp_n * 32 + nt8 * 8 + tr;
            const long co = (long)r * Nn + c0;
            const float2 cr = *(const float2*)(C + co);
            const float2 ci = *(const float2*)(C + NN + co);
            const float vr0 = accD[nt8][2*h]   + cr.x;
            const float vr1 = accD[nt8][2*h+1] + cr.y;
            const float vi0 = accM[nt8][2*h]   + ci.x;
            const float vi1 = accM[nt8][2*h+1] + ci.y;
            const long or_ = ((long)b * 2 + 0) * NN + co;
            const long oi_ = ((long)b * 2 + 1) * NN + co;
            if (isFinal) {
                *(float2*)(outF + or_) = make_float2(vr0, vr1);
                *(float2*)(outF + oi_) = make_float2(vi0, vi1);
            } else {
                __half2 hv;
                hv.x = __float2half_rn(vr0); hv.y = __float2half_rn(vr1);
                *(__half2*)(outH + or_) = hv;
                hv.x = __float2half_rn(vi0); hv.y = __float2half_rn(vi1);
                *(__half2*)(outH + oi_) = hv;
            }
        }
}

// ---------------------------------------------------------------------------
extern "C" void kernel_launch(void* const* d_in, const int* in_sizes, int n_in,
                              void* d_out, int out_size)
{
    const float* x      = (const float*)d_in[0];
    const float* coeffs = (const float*)d_in[1];
    if (n_in >= 2 && in_sizes[0] == 8 * 2 * NN) {
        const float* t = x; x = coeffs; coeffs = t;
    }

    __half *xtH, *s0H, *s1H, *c7H;
    cudaGetSymbolAddress((void**)&xtH, g_xt_h);
    cudaGetSymbolAddress((void**)&s0H, g_s0_h);
    cudaGetSymbolAddress((void**)&s1H, g_s1_h);
    cudaGetSymbolAddress((void**)&c7H, g_c7_h);

    cudaFuncSetAttribute(cgemm_mma, cudaFuncAttributeMaxDynamicSharedMemorySize, SMEM_BYTES);

    x_transpose_h<<<dim3(16, 16, 128), 256>>>(x, xtH);
    conv_c7<<<(2 * NN + 255) / 256, 256>>>(coeffs + (long)7 * 2 * NN, c7H);

    dim3 grid(Nn / BN, Nn / BM, BATCH);   // (8, 8, 64)
    dim3 block(256);

    const __half* aP = c7H;
    long aStride = 0;
    __half* dstH[7] = {s0H, s1H, s0H, s1H, s0H, s1H, nullptr};

    for (int t = 0; t < 7; ++t) {
        const float* Ct = coeffs + (long)(6 - t) * 2 * NN;
        const int fin = (t == 6);
        cgemm_mma<<<grid, block, SMEM_BYTES>>>(
            aP, aStride, xtH, Ct,
            fin ? (float*)d_out : nullptr, dstH[t], fin);
        aP = dstH[t];
        aStride = 2L * NN;
    }
}

// round 12
// speedup vs baseline: 1.0280x; 1.0093x over previous
#include <cuda_runtime.h>
#include <cuda_fp16.h>
#include <cstdint>

#define Nn    512
#define NN    (Nn * Nn)
#define BATCH 64
#define KCH   32
#define NCHUNK (Nn / KCH)        // 16
#define BM 64
#define BN 64
#define MAT_A 8192               // 64 rows x 128B [ArH k32 | AiH k32]
#define STG_B 16384              // A (8KB) + X (8KB)
#define NSTG 4
#define SMEM_BYTES (NSTG * STG_B + 1024)

// ---------------- global scratch ----------------
__device__ __half g_xt_h[(size_t)BATCH * 2 * NN];   // X^T single fp16
__device__ __half g_s0_h[(size_t)BATCH * 2 * NN];   // S ping-pong, single fp16
__device__ __half g_s1_h[(size_t)BATCH * 2 * NN];
__device__ __half g_c7_h[(size_t)2 * NN];

// ---------------- helpers ----------------
__device__ __forceinline__ uint32_t smem_u32(const void* p) {
    uint32_t a;
    asm("{ .reg .u64 t; cvta.to.shared.u64 t, %1; cvt.u32.u64 %0, t; }" : "=r"(a) : "l"(p));
    return a;
}
#define CP_ASYNC16(dst, src) \
    asm volatile("cp.async.cg.shared.global [%0], [%1], 16;" :: "r"(dst), "l"(src))
#define CP_COMMIT()  asm volatile("cp.async.commit_group;" ::: "memory")
#define CP_WAIT2()   asm volatile("cp.async.wait_group 2;" ::: "memory")
#define CP_WAIT1()   asm volatile("cp.async.wait_group 1;" ::: "memory")
#define CP_WAIT0()   asm volatile("cp.async.wait_group 0;" ::: "memory")

__device__ __forceinline__ void ldsm4(uint32_t* r, uint32_t addr) {
    asm volatile("ldmatrix.sync.aligned.m8n8.x4.shared.b16 {%0,%1,%2,%3}, [%4];"
                 : "=r"(r[0]), "=r"(r[1]), "=r"(r[2]), "=r"(r[3]) : "r"(addr));
}
__device__ __forceinline__ void mma16816(float* d, const uint32_t* a, const uint32_t* b) {
    asm volatile(
        "mma.sync.aligned.m16n8k16.row.col.f32.f16.f16.f32 "
        "{%0,%1,%2,%3}, {%4,%5,%6,%7}, {%8,%9}, {%0,%1,%2,%3};"
        : "+f"(d[0]), "+f"(d[1]), "+f"(d[2]), "+f"(d[3])
        : "r"(a[0]), "r"(a[1]), "r"(a[2]), "r"(a[3]), "r"(b[0]), "r"(b[1]));
}

// ---------------------------------------------------------------------------
__global__ void x_transpose_h(const float* __restrict__ x,
                              __half* __restrict__ xh)
{
    __shared__ float t[32][33];
    const int z  = blockIdx.z;
    const int k0 = blockIdx.y * 32;
    const int n0 = blockIdx.x * 32;
    const int tx = threadIdx.x & 31, ty = threadIdx.x >> 5;
    const long zb = (long)z * NN;
    #pragma unroll
    for (int i = 0; i < 4; ++i)
        t[ty + 8 * i][tx] = x[zb + (long)(k0 + ty + 8 * i) * Nn + n0 + tx];
    __syncthreads();
    #pragma unroll
    for (int i = 0; i < 4; ++i) {
        const int n = n0 + ty + 8 * i, k = k0 + tx;
        xh[zb + (long)n * Nn + k] = __float2half_rn(t[tx][ty + 8 * i]);
    }
}

__global__ void conv_c7(const float* __restrict__ c7, __half* __restrict__ h)
{
    const int i = blockIdx.x * 256 + threadIdx.x;
    if (i < 2 * NN) h[i] = __float2half_rn(c7[i]);
}

// ---------------------------------------------------------------------------
// Fused complex GEMM, single-fp16, 4 passes, 3 CTAs/SM (6 warps/SMSP):
//   accD = Ar.Xr + (-Ai).Xi ; accM = Ai.Xr + Ar.Xi
// CTA 64x64, 8 warps (2m x 4n), warp tile 32x16, regs <= 85.
// Sign of Ai folded IN PLACE: accM mmas use ai, then ai ^= signbits, then accD.
// 4-stage cp.async pipeline (R8 scheme), phase-staggered k order.
// smem rows pack components: A row = [ArH | AiH], X row = [XrH | XiH].
// ---------------------------------------------------------------------------
__global__ void __launch_bounds__(256, 3) cgemm_mma(
    const __half* __restrict__ aH, long aStride,
    const __half* __restrict__ xH,
    const float* __restrict__ C,
    float* __restrict__ outF,
    __half* __restrict__ outH,
    int isFinal)
{
    extern __shared__ char smraw[];
    const uint32_t sbase = (smem_u32(smraw) + 1023) & ~1023u;

    const int tid  = threadIdx.x;
    const int lane = tid & 31, wid = tid >> 5;
    const int warp_m = wid & 1;          // 2 m-tiles of 32 rows
    const int warp_n = wid >> 1;         // 4 n-tiles of 16 cols
    const int b  = blockIdx.z;
    const int bn = blockIdx.x * BN;
    const int bm = blockIdx.y * BM;

    // Per-CTA k-phase: decorrelate barrier timing of co-resident CTAs.
    const int phase =
        (int)(((blockIdx.x + blockIdx.y * 8u + blockIdx.z * 64u) * 11u) & 15u);

    // ---- cp.async per-thread constants: 4 x 16B per thread per chunk ----
    const int q = tid & 7, rowt = tid >> 3;   // q: 16B chunk in 128B row, rowt 0..31
    const int comp = q >> 2;
    const __half* srcA = aH + (long)b * aStride + (long)comp * NN
                       + (long)(bm + rowt) * Nn + (q & 3) * 8;
    const __half* srcX = xH + ((long)(2 * b) + comp) * NN
                       + (long)(bn + rowt) * Nn + (q & 3) * 8;
    const uint32_t sw0 =
        ((uint32_t)(rowt * 128 + q * 16)) ^ (uint32_t)((rowt & 7) << 4);
    const uint32_t sw1 =
        ((uint32_t)((rowt + 32) * 128 + q * 16)) ^ (uint32_t)((rowt & 7) << 4);

    auto issue = [&](int c) {
        const uint32_t sd = sbase + (uint32_t)(c & 3) * STG_B;
        const long kadd = (long)(((c + phase) & (NCHUNK - 1)) * KCH);
        CP_ASYNC16(sd + sw0,                    srcA + kadd);
        CP_ASYNC16(sd + sw1,                    srcA + kadd + 32L * Nn);
        CP_ASYNC16(sd + (uint32_t)MAT_A + sw0,  srcX + kadd);
        CP_ASYNC16(sd + (uint32_t)MAT_A + sw1,  srcX + kadd + 32L * Nn);
        CP_COMMIT();
    };

    // ---- ldmatrix per-lane constants ----
    const uint32_t amask = (uint32_t)((lane & 7) << 4);
    const uint32_t abase = (uint32_t)((warp_m * 32 + (lane & 15)) * 128 + (lane >> 4) * 16);
    const uint32_t bbase =
        (uint32_t)((warp_n * 16 + ((lane & 7) | ((lane >> 1) & 8))) * 128
                   + ((lane >> 3) & 1) * 16);

    float accD[2][2][4], accM[2][2][4];
    #pragma unroll
    for (int i = 0; i < 2; ++i)
        #pragma unroll
        for (int j = 0; j < 2; ++j)
            #pragma unroll
            for (int k = 0; k < 4; ++k) { accD[i][j][k] = 0.f; accM[i][j][k] = 0.f; }

    issue(0); issue(1); issue(2);

    for (int c = 0; c < NCHUNK; ++c) {
        if (c < NCHUNK - 2)       CP_WAIT2();
        else if (c == NCHUNK - 2) CP_WAIT1();
        else                      CP_WAIT0();
        __syncthreads();

        const uint32_t st = sbase + (uint32_t)(c & 3) * STG_B;
        #pragma unroll
        for (int sl = 0; sl < 2; ++sl) {
            uint32_t ar[2][4], ai[2][4];
            #pragma unroll
            for (int mt = 0; mt < 2; ++mt) {
                const uint32_t rh =
                    (abase + (uint32_t)mt * 2048u + (uint32_t)sl * 32u) ^ amask;
                ldsm4(ar[mt], st + rh);             // Ar half (m16k16)
                ldsm4(ai[mt], st + (rh ^ 64u));     // Ai half
            }
            const uint32_t bb = (bbase + (uint32_t)sl * 32u) ^ amask;
            uint32_t br[4], bi[4];
            ldsm4(br, st + (uint32_t)MAT_A + bb);            // Xr (n16k16)
            ldsm4(bi, st + (uint32_t)MAT_A + (bb ^ 64u));    // Xi

            // accM += Ai.Xr + Ar.Xi  (uses ai BEFORE sign flip)
            #pragma unroll
            for (int mt = 0; mt < 2; ++mt)
                #pragma unroll
                for (int nt = 0; nt < 2; ++nt) {
                    mma16816(accM[mt][nt], ai[mt], br + nt * 2);
                    mma16816(accM[mt][nt], ar[mt], bi + nt * 2);
                }
            // fold sign: ai -> -ai (in place, no extra regs)
            #pragma unroll
            for (int mt = 0; mt < 2; ++mt)
                #pragma unroll
                for (int j = 0; j < 4; ++j) ai[mt][j] ^= 0x80008000u;
            // accD += Ar.Xr + (-Ai).Xi
            #pragma unroll
            for (int mt = 0; mt < 2; ++mt)
                #pragma unroll
                for (int nt = 0; nt < 2; ++nt) {
                    mma16816(accD[mt][nt], ar[mt], br + nt * 2);
                    mma16816(accD[mt][nt], ai[mt], bi + nt * 2);
                }

            // Launch next chunk's loads after the first slice.
            if (sl == 0 && c + 3 < NCHUNK) issue(c + 3);
        }
    }

    // ---- epilogue: Dr = accD + Cr ; Di = accM + Ci ----
    const int tq = lane >> 2, tr = (lane & 3) * 2;
    #pragma unroll
    for (int mt = 0; mt < 2; ++mt)
        #pragma unroll
        for (int nt = 0; nt < 2; ++nt)
            #pragma unroll
            for (int h = 0; h < 2; ++h) {
                const int r  = bm + warp_m * 32 + mt * 16 + h * 8 + tq;
                const int c0 = bn + warp_n * 16 + nt * 8 + tr;
                const long co = (long)r * Nn + c0;
                const float2 cr = *(const float2*)(C + co);
                const float2 ci = *(const float2*)(C + NN + co);
                const float vr0 = accD[mt][nt][2*h]   + cr.x;
                const float vr1 = accD[mt][nt][2*h+1] + cr.y;
                const float vi0 = accM[mt][nt][2*h]   + ci.x;
                const float vi1 = accM[mt][nt][2*h+1] + ci.y;
                const long or_ = ((long)b * 2 + 0) * NN + co;
                const long oi_ = ((long)b * 2 + 1) * NN + co;
                if (isFinal) {
                    *(float2*)(outF + or_) = make_float2(vr0, vr1);
                    *(float2*)(outF + oi_) = make_float2(vi0, vi1);
                } else {
                    __half2 hv;
                    hv.x = __float2half_rn(vr0); hv.y = __float2half_rn(vr1);
                    *(__half2*)(outH + or_) = hv;
                    hv.x = __float2half_rn(vi0); hv.y = __float2half_rn(vi1);
                    *(__half2*)(outH + oi_) = hv;
                }
            }
}

// ---------------------------------------------------------------------------
extern "C" void kernel_launch(void* const* d_in, const int* in_sizes, int n_in,
                              void* d_out, int out_size)
{
    const float* x      = (const float*)d_in[0];
    const float* coeffs = (const float*)d_in[1];
    if (n_in >= 2 && in_sizes[0] == 8 * 2 * NN) {
        const float* t = x; x = coeffs; coeffs = t;
    }

    __half *xtH, *s0H, *s1H, *c7H;
    cudaGetSymbolAddress((void**)&xtH, g_xt_h);
    cudaGetSymbolAddress((void**)&s0H, g_s0_h);
    cudaGetSymbolAddress((void**)&s1H, g_s1_h);
    cudaGetSymbolAddress((void**)&c7H, g_c7_h);

    cudaFuncSetAttribute(cgemm_mma, cudaFuncAttributeMaxDynamicSharedMemorySize, SMEM_BYTES);

    x_transpose_h<<<dim3(16, 16, 128), 256>>>(x, xtH);
    conv_c7<<<(2 * NN + 255) / 256, 256>>>(coeffs + (long)7 * 2 * NN, c7H);

    dim3 grid(Nn / BN, Nn / BM, BATCH);   // (8, 8, 64)
    dim3 block(256);

    const __half* aP = c7H;
    long aStride = 0;
    __half* dstH[7] = {s0H, s1H, s0H, s1H, s0H, s1H, nullptr};

    for (int t = 0; t < 7; ++t) {
        const float* Ct = coeffs + (long)(6 - t) * 2 * NN;
        const int fin = (t == 6);
        cgemm_mma<<<grid, block, SMEM_BYTES>>>(
            aP, aStride, xtH, Ct,
            fin ? (float*)d_out : nullptr, dstH[t], fin);
        aP = dstH[t];
        aStride = 2L * NN;
    }
}

// round 13
// speedup vs baseline: 1.0396x; 1.0113x over previous
#include <cuda_runtime.h>
#include <cuda_fp16.h>
#include <cstdint>

#define Nn    512
#define NN    (Nn * Nn)
#define BATCH 64
#define KCH   32
#define NCHUNK (Nn / KCH)        // 16
#define BM 128
#define BN 64
#define MAT_A 16384              // 128 rows x 128B [ArH k32 | AiH k32]
#define MAT_X 8192               // 64 rows x 128B [XrH k32 | XiH k32]
#define STG_B (MAT_A + MAT_X)    // 24576
#define NSTG 4
#define SMEM_BYTES (NSTG * STG_B + 1024)

// ---------------- global scratch ----------------
__device__ __half g_xt_h[(size_t)BATCH * 2 * NN];   // X^T single fp16
__device__ __half g_s0_h[(size_t)BATCH * 2 * NN];   // S ping-pong, single fp16
__device__ __half g_s1_h[(size_t)BATCH * 2 * NN];
__device__ __half g_c7_h[(size_t)2 * NN];

// ---------------- helpers ----------------
__device__ __forceinline__ uint32_t smem_u32(const void* p) {
    uint32_t a;
    asm("{ .reg .u64 t; cvta.to.shared.u64 t, %1; cvt.u32.u64 %0, t; }" : "=r"(a) : "l"(p));
    return a;
}
#define CP_ASYNC16(dst, src) \
    asm volatile("cp.async.cg.shared.global [%0], [%1], 16;" :: "r"(dst), "l"(src))
#define CP_COMMIT()  asm volatile("cp.async.commit_group;" ::: "memory")
#define CP_WAIT2()   asm volatile("cp.async.wait_group 2;" ::: "memory")
#define CP_WAIT1()   asm volatile("cp.async.wait_group 1;" ::: "memory")
#define CP_WAIT0()   asm volatile("cp.async.wait_group 0;" ::: "memory")

__device__ __forceinline__ void ldsm4(uint32_t* r, uint32_t addr) {
    asm volatile("ldmatrix.sync.aligned.m8n8.x4.shared.b16 {%0,%1,%2,%3}, [%4];"
                 : "=r"(r[0]), "=r"(r[1]), "=r"(r[2]), "=r"(r[3]) : "r"(addr));
}
__device__ __forceinline__ void mma16816(float* d, const uint32_t* a, const uint32_t* b) {
    asm volatile(
        "mma.sync.aligned.m16n8k16.row.col.f32.f16.f16.f32 "
        "{%0,%1,%2,%3}, {%4,%5,%6,%7}, {%8,%9}, {%0,%1,%2,%3};"
        : "+f"(d[0]), "+f"(d[1]), "+f"(d[2]), "+f"(d[3])
        : "r"(a[0]), "r"(a[1]), "r"(a[2]), "r"(a[3]), "r"(b[0]), "r"(b[1]));
}

// ---------------------------------------------------------------------------
__global__ void x_transpose_h(const float* __restrict__ x,
                              __half* __restrict__ xh)
{
    __shared__ float t[32][33];
    const int z  = blockIdx.z;
    const int k0 = blockIdx.y * 32;
    const int n0 = blockIdx.x * 32;
    const int tx = threadIdx.x & 31, ty = threadIdx.x >> 5;
    const long zb = (long)z * NN;
    #pragma unroll
    for (int i = 0; i < 4; ++i)
        t[ty + 8 * i][tx] = x[zb + (long)(k0 + ty + 8 * i) * Nn + n0 + tx];
    __syncthreads();
    #pragma unroll
    for (int i = 0; i < 4; ++i) {
        const int n = n0 + ty + 8 * i, k = k0 + tx;
        xh[zb + (long)n * Nn + k] = __float2half_rn(t[tx][ty + 8 * i]);
    }
}

__global__ void conv_c7(const float* __restrict__ c7, __half* __restrict__ h)
{
    const int i = blockIdx.x * 256 + threadIdx.x;
    if (i < 2 * NN) h[i] = __float2half_rn(c7[i]);
}

// ---------------------------------------------------------------------------
// Fused complex GEMM, single-fp16, 4 passes (R8 skeleton):
//   accD = Ar.Xr + (-Ai).Xi ; accM = Ai.Xr + Ar.Xi
// CTA 128x64, 8 warps (4m x 2n), warp tile 32x32, 2 CTAs/SM,
// 4-stage cp.async pipeline, phase-staggered k order.
// R13 deltas: per-k16-slice ldsm fully hoisted (both ng B frags live),
// mma stream round-robins across all 8 accumulators (ILP 8, no RAW gaps),
// ldsm order staggered by warp parity to spread the crossbar burst.
// ---------------------------------------------------------------------------
__global__ void __launch_bounds__(256, 2) cgemm_mma(
    const __half* __restrict__ aH, long aStride,
    const __half* __restrict__ xH,
    const float* __restrict__ C,
    float* __restrict__ outF,
    __half* __restrict__ outH,
    int isFinal)
{
    extern __shared__ char smraw[];
    const uint32_t sbase = (smem_u32(smraw) + 1023) & ~1023u;

    const int tid  = threadIdx.x;
    const int lane = tid & 31, wid = tid >> 5;
    const int warp_m = wid & 3;          // 4 m-tiles of 32 rows
    const int warp_n = wid >> 2;         // 2 n-tiles of 32 cols
    const int b  = blockIdx.z;
    const int bn = blockIdx.x * BN;
    const int bm = blockIdx.y * BM;

    // Per-CTA k-phase: decorrelate barrier timing of co-resident CTAs.
    const int phase =
        (int)(((blockIdx.x + blockIdx.y * 8u + blockIdx.z * 32u) * 11u) & 15u);

    // ---- cp.async per-thread constants: 6 x 16B per thread per chunk ----
    const int q = tid & 7, rowt = tid >> 3;   // q: 16B chunk in 128B row, rowt: 0..31
    const int comp = (q >= 4);
    const __half* srcs[6];
    uint32_t dsts[6];
    #pragma unroll
    for (int it = 0; it < 6; ++it) {
        if (it < 4) {                          // A: rows rowt + it*32 (0..127)
            const int row = rowt + it * 32;
            srcs[it] = aH + (long)b * aStride + (long)comp * NN
                     + (long)(bm + row) * Nn + (q & 3) * 8;
            dsts[it] = ((uint32_t)(row * 128 + q * 16)) ^ (uint32_t)((row & 7) << 4);
        } else {                               // X: rows rowt + (it-4)*32 (0..63)
            const int row = rowt + (it - 4) * 32;
            srcs[it] = xH + ((long)(2 * b) + comp) * NN
                     + (long)(bn + row) * Nn + (q & 3) * 8;
            dsts[it] = (uint32_t)MAT_A +
                       (((uint32_t)(row * 128 + q * 16)) ^ (uint32_t)((row & 7) << 4));
        }
    }

    auto issue = [&](int c) {
        const uint32_t sd = sbase + (uint32_t)(c % NSTG) * STG_B;
        const long kadd = (long)(((c + phase) & (NCHUNK - 1)) * KCH);
        #pragma unroll
        for (int it = 0; it < 6; ++it)
            CP_ASYNC16(sd + dsts[it], srcs[it] + kadd);
        CP_COMMIT();
    };

    // ---- ldmatrix per-lane constants ----
    const uint32_t amask = (uint32_t)((lane & 7) << 4);
    const uint32_t abase = (uint32_t)((warp_m * 32 + (lane & 15)) * 128 + (lane >> 4) * 16);
    const uint32_t brow  = (uint32_t)((lane & 7) | ((lane >> 1) & 8));
    const uint32_t bcol  = (uint32_t)(((lane >> 3) & 1) * 16);

    float accD[2][4][4], accM[2][4][4];
    #pragma unroll
    for (int i = 0; i < 2; ++i)
        #pragma unroll
        for (int j = 0; j < 4; ++j)
            #pragma unroll
            for (int k = 0; k < 4; ++k) { accD[i][j][k] = 0.f; accM[i][j][k] = 0.f; }

    issue(0); issue(1); issue(2);

    for (int c = 0; c < NCHUNK; ++c) {
        if (c < NCHUNK - 2)       CP_WAIT2();
        else if (c == NCHUNK - 2) CP_WAIT1();
        else                      CP_WAIT0();
        __syncthreads();

        const uint32_t st = sbase + (uint32_t)(c & 3) * STG_B;
        #pragma unroll
        for (int sl = 0; sl < 2; ++sl) {
            // ---- hoisted ldsm: all frags for this k16 slice ----
            uint32_t ar[2][4], ai[2][4];     // 2 m-tiles
            uint32_t br[2][4], bi[2][4];     // 2 n-groups
            const uint32_t rh0 = (abase + (uint32_t)sl * 32u) ^ amask;
            const uint32_t rh1 = (abase + 2048u + (uint32_t)sl * 32u) ^ amask;
            const uint32_t bb0 =
                ((uint32_t)((warp_n * 32 + 0 * 16 + brow) * 128) + bcol
                 + (uint32_t)sl * 32u) ^ amask;
            const uint32_t bb1 =
                ((uint32_t)((warp_n * 32 + 1 * 16 + brow) * 128) + bcol
                 + (uint32_t)sl * 32u) ^ amask;
            if (wid & 1) {   // odd warps: B first (spread the crossbar burst)
                ldsm4(br[0], st + (uint32_t)MAT_A + bb0);
                ldsm4(bi[0], st + (uint32_t)MAT_A + (bb0 ^ 64u));
                ldsm4(br[1], st + (uint32_t)MAT_A + bb1);
                ldsm4(bi[1], st + (uint32_t)MAT_A + (bb1 ^ 64u));
                ldsm4(ar[0], st + rh0);
                ldsm4(ai[0], st + (rh0 ^ 64u));
                ldsm4(ar[1], st + rh1);
                ldsm4(ai[1], st + (rh1 ^ 64u));
            } else {
                ldsm4(ar[0], st + rh0);
                ldsm4(ai[0], st + (rh0 ^ 64u));
                ldsm4(ar[1], st + rh1);
                ldsm4(ai[1], st + (rh1 ^ 64u));
                ldsm4(br[0], st + (uint32_t)MAT_A + bb0);
                ldsm4(bi[0], st + (uint32_t)MAT_A + (bb0 ^ 64u));
                ldsm4(br[1], st + (uint32_t)MAT_A + bb1);
                ldsm4(bi[1], st + (uint32_t)MAT_A + (bb1 ^ 64u));
            }

            // ---- mma stream: round-robin over 8 accs, 4 passes ----
            // pass 1: accM += Ai.Xr     (8 mmas, accs M[0][0..3], M[1][0..3])
            #pragma unroll
            for (int mt = 0; mt < 2; ++mt)
                #pragma unroll
                for (int j = 0; j < 4; ++j)
                    mma16816(accM[mt][j], ai[mt], br[j >> 1] + (j & 1) * 2);
            // pass 2: accD += Ar.Xr
            #pragma unroll
            for (int mt = 0; mt < 2; ++mt)
                #pragma unroll
                for (int j = 0; j < 4; ++j)
                    mma16816(accD[mt][j], ar[mt], br[j >> 1] + (j & 1) * 2);
            // pass 3: accM += Ar.Xi
            #pragma unroll
            for (int mt = 0; mt < 2; ++mt)
                #pragma unroll
                for (int j = 0; j < 4; ++j)
                    mma16816(accM[mt][j], ar[mt], bi[j >> 1] + (j & 1) * 2);
            // fold sign in place: ai -> -ai
            #pragma unroll
            for (int mt = 0; mt < 2; ++mt)
                #pragma unroll
                for (int k = 0; k < 4; ++k) ai[mt][k] ^= 0x80008000u;
            // pass 4: accD += (-Ai).Xi
            #pragma unroll
            for (int mt = 0; mt < 2; ++mt)
                #pragma unroll
                for (int j = 0; j < 4; ++j)
                    mma16816(accD[mt][j], ai[mt], bi[j >> 1] + (j & 1) * 2);

            // Launch next chunk's loads after the first slice.
            if (sl == 0 && c + 3 < NCHUNK) issue(c + 3);
        }
    }

    // ---- epilogue: Dr = accD + Cr ; Di = accM + Ci ----
    const int tq = lane >> 2, tr = (lane & 3) * 2;
    #pragma unroll
    for (int mt = 0; mt < 2; ++mt)
        #pragma unroll
        for (int j = 0; j < 4; ++j)
            #pragma unroll
            for (int h = 0; h < 2; ++h) {
                const int r  = bm + warp_m * 32 + mt * 16 + h * 8 + tq;
                const int c0 = bn + warp_n * 32 + j * 8 + tr;
                const long co = (long)r * Nn + c0;
                const float2 cr = *(const float2*)(C + co);
                const float2 ci = *(const float2*)(C + NN + co);
                const float vr0 = accD[mt][j][2*h]   + cr.x;
                const float vr1 = accD[mt][j][2*h+1] + cr.y;
                const float vi0 = accM[mt][j][2*h]   + ci.x;
                const float vi1 = accM[mt][j][2*h+1] + ci.y;
                const long or_ = ((long)b * 2 + 0) * NN + co;
                const long oi_ = ((long)b * 2 + 1) * NN + co;
                if (isFinal) {
                    *(float2*)(outF + or_) = make_float2(vr0, vr1);
                    *(float2*)(outF + oi_) = make_float2(vi0, vi1);
                } else {
                    __half2 hv;
                    hv.x = __float2half_rn(vr0); hv.y = __float2half_rn(vr1);
                    *(__half2*)(outH + or_) = hv;
                    hv.x = __float2half_rn(vi0); hv.y = __float2half_rn(vi1);
                    *(__half2*)(outH + oi_) = hv;
                }
            }
}

// ---------------------------------------------------------------------------
extern "C" void kernel_launch(void* const* d_in, const int* in_sizes, int n_in,
                              void* d_out, int out_size)
{
    const float* x      = (const float*)d_in[0];
    const float* coeffs = (const float*)d_in[1];
    if (n_in >= 2 && in_sizes[0] == 8 * 2 * NN) {
        const float* t = x; x = coeffs; coeffs = t;
    }

    __half *xtH, *s0H, *s1H, *c7H;
    cudaGetSymbolAddress((void**)&xtH, g_xt_h);
    cudaGetSymbolAddress((void**)&s0H, g_s0_h);
    cudaGetSymbolAddress((void**)&s1H, g_s1_h);
    cudaGetSymbolAddress((void**)&c7H, g_c7_h);

    cudaFuncSetAttribute(cgemm_mma, cudaFuncAttributeMaxDynamicSharedMemorySize, SMEM_BYTES);

    x_transpose_h<<<dim3(16, 16, 128), 256>>>(x, xtH);
    conv_c7<<<(2 * NN + 255) / 256, 256>>>(coeffs + (long)7 * 2 * NN, c7H);

    dim3 grid(Nn / BN, Nn / BM, BATCH);   // (8, 4, 64)
    dim3 block(256);

    const __half* aP = c7H;
    long aStride = 0;
    __half* dstH[7] = {s0H, s1H, s0H, s1H, s0H, s1H, nullptr};

    for (int t = 0; t < 7; ++t) {
        const float* Ct = coeffs + (long)(6 - t) * 2 * NN;
        const int fin = (t == 6);
        cgemm_mma<<<grid, block, SMEM_BYTES>>>(
            aP, aStride, xtH, Ct,
            fin ? (float*)d_out : nullptr, dstH[t], fin);
        aP = dstH[t];
        aStride = 2L * NN;
    }
}